// round 2
// baseline (speedup 1.0000x reference)
#include <cuda_runtime.h>
#include <cuda_bf16.h>
#include <stdint.h>

#define NB 16
#define NN 1024
#define DD 64
#define OUT_OFF ((size_t)NB * NN * NN)

// ---------------- scratch (device globals; no allocation) ----------------
__device__ float g_rowmean[NB*NN];
__device__ float g_diag[NB*NN];
__device__ float g_r[NB*NN];            // c3*rowmean + c4*diag + p1
__device__ float g_s[NB];               // c1*mean_all + c2*mean_diag + p2
__device__ float g_pg1[NB*DD];
__device__ float g_pg2[NB*DD];
__device__ float g_X2tT[(size_t)NB*DD*NN];   // X2_t transposed: [b][e][j]

// ---------------- packed fp32x2 helpers ----------------
__device__ __forceinline__ void fma2(unsigned long long &d,
                                     unsigned long long a,
                                     unsigned long long b) {
    asm("fma.rn.f32x2 %0, %1, %2, %0;" : "+l"(d) : "l"(a), "l"(b));
}
__device__ __forceinline__ float psum(unsigned long long v) {
    return __uint_as_float((unsigned)v) + __uint_as_float((unsigned)(v >> 32));
}

// ---------------- kernel 1: per-row stats (rowmean, diag, r) -------------
__global__ __launch_bounds__(256) void k_row_stats(
    const float* __restrict__ A, const float* __restrict__ X,
    const float* __restrict__ coeffs, const float* __restrict__ wA1)
{
    int gw = blockIdx.x * 8 + (threadIdx.x >> 5);   // global row 0..16383
    int lane = threadIdx.x & 31;
    const float4* arow = reinterpret_cast<const float4*>(A) + (size_t)gw * (NN/4);
    float s = 0.f;
#pragma unroll
    for (int w = 0; w < 8; ++w) {
        float4 v = arow[lane + (w << 5)];
        s += (v.x + v.y) + (v.z + v.w);
    }
    const float* xrow = X + (size_t)gw * DD;
    float p = xrow[lane] * wA1[lane] + xrow[lane+32] * wA1[lane+32];
#pragma unroll
    for (int o = 16; o; o >>= 1) {
        s += __shfl_xor_sync(0xffffffffu, s, o);
        p += __shfl_xor_sync(0xffffffffu, p, o);
    }
    if (lane == 0) {
        int i = gw & (NN-1);
        float d = A[(size_t)gw*NN + i];
        float rm = s * (1.f/NN);
        g_rowmean[gw] = rm;
        g_diag[gw]    = d;
        g_r[gw]       = coeffs[3]*rm + coeffs[4]*d + p;
    }
}

// ---------------- kernel 2: per-batch stats (s, pg1, pg2) ----------------
__global__ __launch_bounds__(256) void k_batch_stats(
    const float* __restrict__ X, const float* __restrict__ coeffs,
    const float* __restrict__ wA2,
    const float* __restrict__ w12, const float* __restrict__ w15, const float* __restrict__ w16,
    const float* __restrict__ w22, const float* __restrict__ w25, const float* __restrict__ w26)
{
    int b = blockIdx.x, t = threadIdx.x;
    __shared__ float red[256];
    __shared__ float sm_meanX[DD];
    __shared__ float sm_mall, sm_mdiag;

    float v1 = 0.f, v2 = 0.f;
    for (int i = t; i < NN; i += 256) { v1 += g_rowmean[b*NN+i]; v2 += g_diag[b*NN+i]; }
    red[t] = v1; __syncthreads();
    for (int o = 128; o > 0; o >>= 1) { if (t < o) red[t] += red[t+o]; __syncthreads(); }
    if (t == 0) sm_mall = red[0]*(1.f/NN);
    __syncthreads();
    red[t] = v2; __syncthreads();
    for (int o = 128; o > 0; o >>= 1) { if (t < o) red[t] += red[t+o]; __syncthreads(); }
    if (t == 0) sm_mdiag = red[0]*(1.f/NN);
    __syncthreads();

    int d = t & 63, g = t >> 6;
    float xs = 0.f;
    for (int j = g; j < NN; j += 4) xs += X[((size_t)b*NN + j)*DD + d];
    red[t] = xs; __syncthreads();
    if (g == 0) sm_meanX[d] = (red[d] + red[d+64] + red[d+128] + red[d+192]) * (1.f/NN);
    __syncthreads();

    float mall = sm_mall, mdiag = sm_mdiag;
    if (t == 0) {
        float p2 = 0.f;
        for (int k = 0; k < DD; ++k) p2 += sm_meanX[k]*wA2[k];
        g_s[b] = coeffs[1]*mall + coeffs[2]*mdiag + p2;
    } else if (t >= 64 && t < 128) {
        int e = t - 64;
        float a = 0.f;
        for (int k = 0; k < DD; ++k) a += sm_meanX[k]*w12[e*DD+k];
        g_pg1[b*DD+e] = a + mdiag*w15[e] + mall*w16[e];
    } else if (t >= 128 && t < 192) {
        int e = t - 128;
        float a = 0.f;
        for (int k = 0; k < DD; ++k) a += sm_meanX[k]*w22[e*DD+k];
        g_pg2[b*DD+e] = a + mdiag*w25[e] + mall*w26[e];
    }
}

// ---------------- kernel 3: node transforms X1_t, X2_t^T -----------------
// dynamic smem: Xs[128*64] | W1[64*68] | W2[64*68]  (67584 B)
__global__ __launch_bounds__(256) void k_node(
    const float* __restrict__ X,
    const float* __restrict__ w11, const float* __restrict__ w13, const float* __restrict__ w14,
    const float* __restrict__ w21, const float* __restrict__ w23, const float* __restrict__ w24,
    float* __restrict__ x1o)
{
    extern __shared__ __align__(16) float sm[];
    float* Xs = sm;               // [128][64]
    float* W1 = sm + 128*DD;      // [64][68]
    float* W2 = W1 + 64*68;       // [64][68]

    const int b = blockIdx.y;
    const int it0 = blockIdx.x << 7;    // 128 rows per block
    const int tid = threadIdx.x;
    const int c4 = tid & 15, r0 = tid >> 4;   // r0 0..15
    const int ci = c4 << 2;

    const float* Xb = X + ((size_t)b*NN + it0)*DD;
#pragma unroll
    for (int t = 0; t < 8; ++t) {
        int row = r0 + (t << 4);
        *reinterpret_cast<float4*>(Xs + row*DD + ci) =
            *reinterpret_cast<const float4*>(Xb + (size_t)row*DD + ci);
    }
#pragma unroll
    for (int t = 0; t < 4; ++t) {
        int e = r0 + (t << 4);
        *reinterpret_cast<float4*>(W1 + e*68 + ci) = *reinterpret_cast<const float4*>(w11 + e*DD + ci);
        *reinterpret_cast<float4*>(W2 + e*68 + ci) = *reinterpret_cast<const float4*>(w21 + e*DD + ci);
    }
    __syncthreads();

    const int tx = tid & 15, ty = tid >> 4;
    const int e0 = tx << 2, i0 = ty << 3;   // i0 0..120

    float rmv[8], dgv[8];
#pragma unroll
    for (int r = 0; r < 8; ++r) {
        int row = b*NN + it0 + i0 + r;
        rmv[r] = g_rowmean[row];
        dgv[r] = g_diag[row];
    }

    unsigned long long acc[8][4];

    // ---- pass 1: X1_t -> x1o ----
#pragma unroll
    for (int r = 0; r < 8; ++r)
#pragma unroll
        for (int q = 0; q < 4; ++q) acc[r][q] = 0ull;
#pragma unroll 2
    for (int d = 0; d < DD; d += 4) {
        ulonglong2 a[8];
#pragma unroll
        for (int r = 0; r < 8; ++r)
            a[r] = *reinterpret_cast<const ulonglong2*>(Xs + (i0+r)*DD + d);
#pragma unroll
        for (int q = 0; q < 4; ++q) {
            ulonglong2 bv = *reinterpret_cast<const ulonglong2*>(W1 + (e0+q)*68 + d);
#pragma unroll
            for (int r = 0; r < 8; ++r) { fma2(acc[r][q], a[r].x, bv.x); fma2(acc[r][q], a[r].y, bv.y); }
        }
    }
    {
        float4 wc = *reinterpret_cast<const float4*>(w13 + e0);
        float4 wd = *reinterpret_cast<const float4*>(w14 + e0);
        float4 pg = *reinterpret_cast<const float4*>(g_pg1 + b*DD + e0);
#pragma unroll
        for (int r = 0; r < 8; ++r) {
            float4 o;
            o.x = psum(acc[r][0]) + rmv[r]*wc.x + dgv[r]*wd.x + pg.x;
            o.y = psum(acc[r][1]) + rmv[r]*wc.y + dgv[r]*wd.y + pg.y;
            o.z = psum(acc[r][2]) + rmv[r]*wc.z + dgv[r]*wd.z + pg.z;
            o.w = psum(acc[r][3]) + rmv[r]*wc.w + dgv[r]*wd.w + pg.w;
            *reinterpret_cast<float4*>(x1o + ((size_t)b*NN + it0 + i0 + r)*DD + e0) = o;
        }
    }

    // ---- pass 2: X2_t -> registers, then SMEM-bounce transpose ----
#pragma unroll
    for (int r = 0; r < 8; ++r)
#pragma unroll
        for (int q = 0; q < 4; ++q) acc[r][q] = 0ull;
#pragma unroll 2
    for (int d = 0; d < DD; d += 4) {
        ulonglong2 a[8];
#pragma unroll
        for (int r = 0; r < 8; ++r)
            a[r] = *reinterpret_cast<const ulonglong2*>(Xs + (i0+r)*DD + d);
#pragma unroll
        for (int q = 0; q < 4; ++q) {
            ulonglong2 bv = *reinterpret_cast<const ulonglong2*>(W2 + (e0+q)*68 + d);
#pragma unroll
            for (int r = 0; r < 8; ++r) { fma2(acc[r][q], a[r].x, bv.x); fma2(acc[r][q], a[r].y, bv.y); }
        }
    }
    float4 o2v[8];
    {
        float4 wc = *reinterpret_cast<const float4*>(w23 + e0);
        float4 wd = *reinterpret_cast<const float4*>(w24 + e0);
        float4 pg = *reinterpret_cast<const float4*>(g_pg2 + b*DD + e0);
#pragma unroll
        for (int r = 0; r < 8; ++r) {
            o2v[r].x = psum(acc[r][0]) + rmv[r]*wc.x + dgv[r]*wd.x + pg.x;
            o2v[r].y = psum(acc[r][1]) + rmv[r]*wc.y + dgv[r]*wd.y + pg.y;
            o2v[r].z = psum(acc[r][2]) + rmv[r]*wc.z + dgv[r]*wd.z + pg.z;
            o2v[r].w = psum(acc[r][3]) + rmv[r]*wc.w + dgv[r]*wd.w + pg.w;
        }
    }
    __syncthreads();   // all reads of Xs done -> reuse as transpose buffer T[128][64]
#pragma unroll
    for (int r = 0; r < 8; ++r)
        *reinterpret_cast<float4*>(Xs + (i0+r)*DD + e0) = o2v[r];
    __syncthreads();

    // transposed write: g_X2tT[b][e][j]
    const int e = tid & 63, rc = tid >> 6;   // rc 0..3
#pragma unroll
    for (int rr = 0; rr < 8; ++rr) {
        int rowl = (rc << 5) + (rr << 2);
        float4 v;
        v.x = Xs[(rowl+0)*DD + e];
        v.y = Xs[(rowl+1)*DD + e];
        v.z = Xs[(rowl+2)*DD + e];
        v.w = Xs[(rowl+3)*DD + e];
        *reinterpret_cast<float4*>(g_X2tT + ((size_t)b*DD + e)*NN + it0 + rowl) = v;
    }
}

// ---------------- kernel 4: fused A_t construction + GEMM ----------------
// 64x64 output tile per 128-thread block; k-paired fp32x2 accumulation.
__global__ __launch_bounds__(128, 2) void k_gemm(
    const float* __restrict__ A, const float* __restrict__ coeffs,
    float* __restrict__ At, float* __restrict__ x1o)
{
    __shared__ __align__(16) float Ast[64*68];   // [i_loc][k_loc]
    __shared__ __align__(16) float Bst[64*68];   // [e][k_loc]

    const int b = blockIdx.y, it0 = blockIdx.x << 6;
    const int tid = threadIdx.x;
    const int c4 = tid & 15, r0 = tid >> 4;    // r0 0..7
    const int ci = c4 << 2;
    const int tx = tid & 15, ty = tid >> 4;
    const int e0 = tx << 2, i0 = ty << 3;

    const float c0 = coeffs[0];
    const float sb = g_s[b];
    float rloc[8];                              // s + r_i, per owned load row
#pragma unroll
    for (int t = 0; t < 8; ++t) rloc[t] = sb + g_r[b*NN + it0 + r0 + (t << 3)];

    const float* Ab = A  + ((size_t)b*NN + it0)*NN;
    float*       Ob = At + ((size_t)b*NN + it0)*NN;
    const float* Bb = g_X2tT + (size_t)b*DD*NN;

    unsigned long long acc[8][4];
#pragma unroll
    for (int r = 0; r < 8; ++r)
#pragma unroll
        for (int q = 0; q < 4; ++q) acc[r][q] = 0ull;

    for (int kt = 0; kt < 16; ++kt) {
        const int k0 = kt << 6;
        __syncthreads();   // previous tile's compute done
#pragma unroll
        for (int t = 0; t < 8; ++t) {
            int erow = r0 + (t << 3);
            float4 bv = *reinterpret_cast<const float4*>(Bb + (size_t)erow*NN + k0 + ci);
            *reinterpret_cast<float4*>(Bst + erow*68 + ci) = bv;
        }
        float4 rj = *reinterpret_cast<const float4*>(g_r + b*NN + k0 + ci);
#pragma unroll
        for (int t = 0; t < 8; ++t) {
            int row = r0 + (t << 3);
            float4 av = *reinterpret_cast<const float4*>(Ab + (size_t)row*NN + k0 + ci);
            float4 atv;
            atv.x = fmaf(c0, av.x, rloc[t] + rj.x);
            atv.y = fmaf(c0, av.y, rloc[t] + rj.y);
            atv.z = fmaf(c0, av.z, rloc[t] + rj.z);
            atv.w = fmaf(c0, av.w, rloc[t] + rj.w);
            *reinterpret_cast<float4*>(Ob + (size_t)row*NN + k0 + ci) = atv;   // A_t out
            *reinterpret_cast<float4*>(Ast + row*68 + ci) = atv;
        }
        __syncthreads();
#pragma unroll 2
        for (int kk = 0; kk < 64; kk += 4) {
            ulonglong2 a[8];
#pragma unroll
            for (int r = 0; r < 8; ++r)
                a[r] = *reinterpret_cast<const ulonglong2*>(Ast + (i0+r)*68 + kk);
#pragma unroll
            for (int q = 0; q < 4; ++q) {
                ulonglong2 bv = *reinterpret_cast<const ulonglong2*>(Bst + (e0+q)*68 + kk);
#pragma unroll
                for (int r = 0; r < 8; ++r) { fma2(acc[r][q], a[r].x, bv.x); fma2(acc[r][q], a[r].y, bv.y); }
            }
        }
    }

    const float inv = 1.0f / 1024.0f;
#pragma unroll
    for (int r = 0; r < 8; ++r) {
        size_t off = ((size_t)b*NN + it0 + i0 + r)*DD + e0;
        float4 x1 = *reinterpret_cast<const float4*>(x1o + off);
        float4 o;
        o.x = psum(acc[r][0])*inv + x1.x;
        o.y = psum(acc[r][1])*inv + x1.y;
        o.z = psum(acc[r][2])*inv + x1.z;
        o.w = psum(acc[r][3])*inv + x1.w;
        *reinterpret_cast<float4*>(x1o + off) = o;
    }
}

// ---------------- launch ----------------
extern "C" void kernel_launch(void* const* d_in, const int* in_sizes, int n_in,
                              void* d_out, int out_size)
{
    const float* A      = (const float*)d_in[0];
    const float* X      = (const float*)d_in[1];
    const float* coeffs = (const float*)d_in[2];
    const float* wA1    = (const float*)d_in[3];
    const float* wA2    = (const float*)d_in[4];
    const float* w11    = (const float*)d_in[5];
    const float* w12    = (const float*)d_in[6];
    const float* w13    = (const float*)d_in[7];
    const float* w14    = (const float*)d_in[8];
    const float* w15    = (const float*)d_in[9];
    const float* w16    = (const float*)d_in[10];
    const float* w21    = (const float*)d_in[11];
    const float* w22    = (const float*)d_in[12];
    const float* w23    = (const float*)d_in[13];
    const float* w24    = (const float*)d_in[14];
    const float* w25    = (const float*)d_in[15];
    const float* w26    = (const float*)d_in[16];

    float* out = (float*)d_out;
    float* x1o = out + OUT_OFF;

    const int NODE_SMEM = (128*DD + 2*64*68) * (int)sizeof(float);  // 67584
    cudaFuncSetAttribute(k_node, cudaFuncAttributeMaxDynamicSharedMemorySize, NODE_SMEM);

    k_row_stats  <<<2048, 256>>>(A, X, coeffs, wA1);
    k_batch_stats<<<16,   256>>>(X, coeffs, wA2, w12, w15, w16, w22, w25, w26);
    k_node       <<<dim3(8,16), 256, NODE_SMEM>>>(X, w11, w13, w14, w21, w23, w24, x1o);
    k_gemm       <<<dim3(16,16), 128>>>(A, coeffs, out, x1o);
}

// round 3
// speedup vs baseline: 1.2921x; 1.2921x over previous
#include <cuda_runtime.h>
#include <cuda_bf16.h>
#include <stdint.h>

#define NB 16
#define NN 1024
#define DD 64
#define OUT_OFF ((size_t)NB * NN * NN)

// ---------------- scratch (device globals; no allocation) ----------------
__device__ float g_rowmean[NB*NN];
__device__ float g_diag[NB*NN];
__device__ float g_r[NB*NN];            // c3*rowmean + c4*diag + p1
__device__ float g_s[NB];               // c1*mean_all + c2*mean_diag + p2
__device__ float g_pg1[NB*DD];
__device__ float g_pg2[NB*DD];
__device__ float g_X2tT[(size_t)NB*DD*NN];   // X2_t transposed: [b][e][j]

// ---------------- packed fp32x2 helpers ----------------
__device__ __forceinline__ void fma2(unsigned long long &d,
                                     unsigned long long a,
                                     unsigned long long b) {
    asm("fma.rn.f32x2 %0, %1, %2, %0;" : "+l"(d) : "l"(a), "l"(b));
}
__device__ __forceinline__ float psum(unsigned long long v) {
    return __uint_as_float((unsigned)v) + __uint_as_float((unsigned)(v >> 32));
}

// ---------------- kernel 1: per-row stats (rowmean, diag, r) -------------
__global__ __launch_bounds__(256) void k_row_stats(
    const float* __restrict__ A, const float* __restrict__ X,
    const float* __restrict__ coeffs, const float* __restrict__ wA1)
{
    int gw = blockIdx.x * 8 + (threadIdx.x >> 5);   // global row 0..16383
    int lane = threadIdx.x & 31;
    const float4* arow = reinterpret_cast<const float4*>(A) + (size_t)gw * (NN/4);
    float s = 0.f;
#pragma unroll
    for (int w = 0; w < 8; ++w) {
        float4 v = arow[lane + (w << 5)];
        s += (v.x + v.y) + (v.z + v.w);
    }
    const float* xrow = X + (size_t)gw * DD;
    float p = xrow[lane] * wA1[lane] + xrow[lane+32] * wA1[lane+32];
#pragma unroll
    for (int o = 16; o; o >>= 1) {
        s += __shfl_xor_sync(0xffffffffu, s, o);
        p += __shfl_xor_sync(0xffffffffu, p, o);
    }
    if (lane == 0) {
        int i = gw & (NN-1);
        float d = A[(size_t)gw*NN + i];
        float rm = s * (1.f/NN);
        g_rowmean[gw] = rm;
        g_diag[gw]    = d;
        g_r[gw]       = coeffs[3]*rm + coeffs[4]*d + p;
    }
}

// ---------------- kernel 2: per-batch stats (s, pg1, pg2) ----------------
__global__ __launch_bounds__(256) void k_batch_stats(
    const float* __restrict__ X, const float* __restrict__ coeffs,
    const float* __restrict__ wA2,
    const float* __restrict__ w12, const float* __restrict__ w15, const float* __restrict__ w16,
    const float* __restrict__ w22, const float* __restrict__ w25, const float* __restrict__ w26)
{
    int b = blockIdx.x, t = threadIdx.x;
    __shared__ float red[256];
    __shared__ float sm_meanX[DD];
    __shared__ float sm_mall, sm_mdiag;

    float v1 = 0.f, v2 = 0.f;
    for (int i = t; i < NN; i += 256) { v1 += g_rowmean[b*NN+i]; v2 += g_diag[b*NN+i]; }
    red[t] = v1; __syncthreads();
    for (int o = 128; o > 0; o >>= 1) { if (t < o) red[t] += red[t+o]; __syncthreads(); }
    if (t == 0) sm_mall = red[0]*(1.f/NN);
    __syncthreads();
    red[t] = v2; __syncthreads();
    for (int o = 128; o > 0; o >>= 1) { if (t < o) red[t] += red[t+o]; __syncthreads(); }
    if (t == 0) sm_mdiag = red[0]*(1.f/NN);
    __syncthreads();

    int d = t & 63, g = t >> 6;
    float xs = 0.f;
    for (int j = g; j < NN; j += 4) xs += X[((size_t)b*NN + j)*DD + d];
    red[t] = xs; __syncthreads();
    if (g == 0) sm_meanX[d] = (red[d] + red[d+64] + red[d+128] + red[d+192]) * (1.f/NN);
    __syncthreads();

    float mall = sm_mall, mdiag = sm_mdiag;
    if (t == 0) {
        float p2 = 0.f;
        for (int k = 0; k < DD; ++k) p2 += sm_meanX[k]*wA2[k];
        g_s[b] = coeffs[1]*mall + coeffs[2]*mdiag + p2;
    } else if (t >= 64 && t < 128) {
        int e = t - 64;
        float a = 0.f;
        for (int k = 0; k < DD; ++k) a += sm_meanX[k]*w12[e*DD+k];
        g_pg1[b*DD+e] = a + mdiag*w15[e] + mall*w16[e];
    } else if (t >= 128 && t < 192) {
        int e = t - 128;
        float a = 0.f;
        for (int k = 0; k < DD; ++k) a += sm_meanX[k]*w22[e*DD+k];
        g_pg2[b*DD+e] = a + mdiag*w25[e] + mall*w26[e];
    }
}

// ---------------- kernel 3: node transforms X1_t, X2_t^T -----------------
// dynamic smem: Xs[128*64] | W1[64*68] | W2[64*68]  (67584 B)
__global__ __launch_bounds__(256) void k_node(
    const float* __restrict__ X,
    const float* __restrict__ w11, const float* __restrict__ w13, const float* __restrict__ w14,
    const float* __restrict__ w21, const float* __restrict__ w23, const float* __restrict__ w24,
    float* __restrict__ x1o)
{
    extern __shared__ __align__(16) float sm[];
    float* Xs = sm;               // [128][64]
    float* W1 = sm + 128*DD;      // [64][68]
    float* W2 = W1 + 64*68;       // [64][68]

    const int b = blockIdx.y;
    const int it0 = blockIdx.x << 7;    // 128 rows per block
    const int tid = threadIdx.x;
    const int c4 = tid & 15, r0 = tid >> 4;   // r0 0..15
    const int ci = c4 << 2;

    const float* Xb = X + ((size_t)b*NN + it0)*DD;
#pragma unroll
    for (int t = 0; t < 8; ++t) {
        int row = r0 + (t << 4);
        *reinterpret_cast<float4*>(Xs + row*DD + ci) =
            *reinterpret_cast<const float4*>(Xb + (size_t)row*DD + ci);
    }
#pragma unroll
    for (int t = 0; t < 4; ++t) {
        int e = r0 + (t << 4);
        *reinterpret_cast<float4*>(W1 + e*68 + ci) = *reinterpret_cast<const float4*>(w11 + e*DD + ci);
        *reinterpret_cast<float4*>(W2 + e*68 + ci) = *reinterpret_cast<const float4*>(w21 + e*DD + ci);
    }
    __syncthreads();

    const int tx = tid & 15, ty = tid >> 4;
    const int e0 = tx << 2, i0 = ty << 3;   // i0 0..120

    float rmv[8], dgv[8];
#pragma unroll
    for (int r = 0; r < 8; ++r) {
        int row = b*NN + it0 + i0 + r;
        rmv[r] = g_rowmean[row];
        dgv[r] = g_diag[row];
    }

    unsigned long long acc[8][4];

    // ---- pass 1: X1_t -> x1o ----
#pragma unroll
    for (int r = 0; r < 8; ++r)
#pragma unroll
        for (int q = 0; q < 4; ++q) acc[r][q] = 0ull;
#pragma unroll 2
    for (int d = 0; d < DD; d += 4) {
        ulonglong2 a[8];
#pragma unroll
        for (int r = 0; r < 8; ++r)
            a[r] = *reinterpret_cast<const ulonglong2*>(Xs + (i0+r)*DD + d);
#pragma unroll
        for (int q = 0; q < 4; ++q) {
            ulonglong2 bv = *reinterpret_cast<const ulonglong2*>(W1 + (e0+q)*68 + d);
#pragma unroll
            for (int r = 0; r < 8; ++r) { fma2(acc[r][q], a[r].x, bv.x); fma2(acc[r][q], a[r].y, bv.y); }
        }
    }
    {
        float4 wc = *reinterpret_cast<const float4*>(w13 + e0);
        float4 wd = *reinterpret_cast<const float4*>(w14 + e0);
        float4 pg = *reinterpret_cast<const float4*>(g_pg1 + b*DD + e0);
#pragma unroll
        for (int r = 0; r < 8; ++r) {
            float4 o;
            o.x = psum(acc[r][0]) + rmv[r]*wc.x + dgv[r]*wd.x + pg.x;
            o.y = psum(acc[r][1]) + rmv[r]*wc.y + dgv[r]*wd.y + pg.y;
            o.z = psum(acc[r][2]) + rmv[r]*wc.z + dgv[r]*wd.z + pg.z;
            o.w = psum(acc[r][3]) + rmv[r]*wc.w + dgv[r]*wd.w + pg.w;
            *reinterpret_cast<float4*>(x1o + ((size_t)b*NN + it0 + i0 + r)*DD + e0) = o;
        }
    }

    // ---- pass 2: X2_t -> registers, then SMEM-bounce transpose ----
#pragma unroll
    for (int r = 0; r < 8; ++r)
#pragma unroll
        for (int q = 0; q < 4; ++q) acc[r][q] = 0ull;
#pragma unroll 2
    for (int d = 0; d < DD; d += 4) {
        ulonglong2 a[8];
#pragma unroll
        for (int r = 0; r < 8; ++r)
            a[r] = *reinterpret_cast<const ulonglong2*>(Xs + (i0+r)*DD + d);
#pragma unroll
        for (int q = 0; q < 4; ++q) {
            ulonglong2 bv = *reinterpret_cast<const ulonglong2*>(W2 + (e0+q)*68 + d);
#pragma unroll
            for (int r = 0; r < 8; ++r) { fma2(acc[r][q], a[r].x, bv.x); fma2(acc[r][q], a[r].y, bv.y); }
        }
    }
    float4 o2v[8];
    {
        float4 wc = *reinterpret_cast<const float4*>(w23 + e0);
        float4 wd = *reinterpret_cast<const float4*>(w24 + e0);
        float4 pg = *reinterpret_cast<const float4*>(g_pg2 + b*DD + e0);
#pragma unroll
        for (int r = 0; r < 8; ++r) {
            o2v[r].x = psum(acc[r][0]) + rmv[r]*wc.x + dgv[r]*wd.x + pg.x;
            o2v[r].y = psum(acc[r][1]) + rmv[r]*wc.y + dgv[r]*wd.y + pg.y;
            o2v[r].z = psum(acc[r][2]) + rmv[r]*wc.z + dgv[r]*wd.z + pg.z;
            o2v[r].w = psum(acc[r][3]) + rmv[r]*wc.w + dgv[r]*wd.w + pg.w;
        }
    }
    __syncthreads();   // all reads of Xs done -> reuse as transpose buffer T[128][64]
#pragma unroll
    for (int r = 0; r < 8; ++r)
        *reinterpret_cast<float4*>(Xs + (i0+r)*DD + e0) = o2v[r];
    __syncthreads();

    // transposed write: g_X2tT[b][e][j]
    const int e = tid & 63, rc = tid >> 6;   // rc 0..3
#pragma unroll
    for (int rr = 0; rr < 8; ++rr) {
        int rowl = (rc << 5) + (rr << 2);
        float4 v;
        v.x = Xs[(rowl+0)*DD + e];
        v.y = Xs[(rowl+1)*DD + e];
        v.z = Xs[(rowl+2)*DD + e];
        v.w = Xs[(rowl+3)*DD + e];
        *reinterpret_cast<float4*>(g_X2tT + ((size_t)b*DD + e)*NN + it0 + rowl) = v;
    }
}

// ---------------- kernel 4: fused A_t construction + GEMM ----------------
// 64x64 tile, 256 threads, 4x4 micro-tile, fp32x2 K-paired accumulation.
// SMEM stored as float4 arrays; B XOR-swizzled for conflict-free reads.
// Register prefetch of next k-tile overlaps LDG latency with compute.
__global__ __launch_bounds__(256, 2) void k_gemm(
    const float* __restrict__ A, const float* __restrict__ coeffs,
    float* __restrict__ At, float* __restrict__ x1o)
{
    __shared__ __align__(16) float4 Ast[64*16];   // phys = row*16 + kc4
    __shared__ __align__(16) float4 Bst[64*16];   // phys = e*16 + (kc4 ^ (e>>2))

    const int b = blockIdx.y, it0 = blockIdx.x << 6;
    const int tid = threadIdx.x;
    const int c4 = tid & 15, r0 = tid >> 4;     // loader coords: col group, base row
    const int ci = c4 << 2;
    const int tx = tid & 15, ty = tid >> 4;     // compute coords
    const int e0 = tx << 2, i0 = ty << 2;       // 4x4 micro-tile

    const float c0 = coeffs[0];
    const float sb = g_s[b];
    float rloc[4];                               // s + r_i for owned load rows
#pragma unroll
    for (int t = 0; t < 4; ++t) rloc[t] = sb + g_r[b*NN + it0 + r0 + (t << 4)];

    const float* Ab = A  + ((size_t)b*NN + it0)*NN;
    float*       Ob = At + ((size_t)b*NN + it0)*NN;
    const float* Bb = g_X2tT + (size_t)b*DD*NN;

    unsigned long long acc[4][4];
#pragma unroll
    for (int r = 0; r < 4; ++r)
#pragma unroll
        for (int q = 0; q < 4; ++q) acc[r][q] = 0ull;

    float4 Ar[4], Br[4], rjv;
    // prologue: prefetch k-tile 0
    rjv = *reinterpret_cast<const float4*>(g_r + b*NN + ci);
#pragma unroll
    for (int t = 0; t < 4; ++t) {
        int row = r0 + (t << 4);
        Ar[t] = *reinterpret_cast<const float4*>(Ab + (size_t)row*NN + ci);
        Br[t] = *reinterpret_cast<const float4*>(Bb + (size_t)row*NN + ci);
    }

    for (int kt = 0; kt < 16; ++kt) {
        const int k0 = kt << 6;
        __syncthreads();   // previous tile's compute done (no-op cost at kt==0)
#pragma unroll
        for (int t = 0; t < 4; ++t) {
            int row = r0 + (t << 4);
            float4 atv;
            atv.x = fmaf(c0, Ar[t].x, rloc[t] + rjv.x);
            atv.y = fmaf(c0, Ar[t].y, rloc[t] + rjv.y);
            atv.z = fmaf(c0, Ar[t].z, rloc[t] + rjv.z);
            atv.w = fmaf(c0, Ar[t].w, rloc[t] + rjv.w);
            *reinterpret_cast<float4*>(Ob + (size_t)row*NN + k0 + ci) = atv;   // A_t out
            Ast[(row << 4) + c4] = atv;
            Bst[(row << 4) + (c4 ^ (row >> 2))] = Br[t];
        }
        __syncthreads();
        if (kt < 15) {   // prefetch next k-tile; LDG latency hidden by compute below
            const int kn = (kt + 1) << 6;
            rjv = *reinterpret_cast<const float4*>(g_r + b*NN + kn + ci);
#pragma unroll
            for (int t = 0; t < 4; ++t) {
                int row = r0 + (t << 4);
                Ar[t] = *reinterpret_cast<const float4*>(Ab + (size_t)row*NN + kn + ci);
                Br[t] = *reinterpret_cast<const float4*>(Bb + (size_t)row*NN + kn + ci);
            }
        }
#pragma unroll
        for (int kc4 = 0; kc4 < 16; ++kc4) {
            ulonglong2 a[4], bv[4];
#pragma unroll
            for (int r = 0; r < 4; ++r)
                a[r] = *reinterpret_cast<const ulonglong2*>(&Ast[((i0+r) << 4) + kc4]);
#pragma unroll
            for (int q = 0; q < 4; ++q)
                bv[q] = *reinterpret_cast<const ulonglong2*>(&Bst[((e0+q) << 4) + (kc4 ^ tx)]);
#pragma unroll
            for (int q = 0; q < 4; ++q)
#pragma unroll
                for (int r = 0; r < 4; ++r) {
                    fma2(acc[r][q], a[r].x, bv[q].x);
                    fma2(acc[r][q], a[r].y, bv[q].y);
                }
        }
    }

    const float inv = 1.0f / 1024.0f;
#pragma unroll
    for (int r = 0; r < 4; ++r) {
        size_t off = ((size_t)b*NN + it0 + i0 + r)*DD + e0;
        float4 x1 = *reinterpret_cast<const float4*>(x1o + off);
        float4 o;
        o.x = psum(acc[r][0])*inv + x1.x;
        o.y = psum(acc[r][1])*inv + x1.y;
        o.z = psum(acc[r][2])*inv + x1.z;
        o.w = psum(acc[r][3])*inv + x1.w;
        *reinterpret_cast<float4*>(x1o + off) = o;
    }
}

// ---------------- launch ----------------
extern "C" void kernel_launch(void* const* d_in, const int* in_sizes, int n_in,
                              void* d_out, int out_size)
{
    const float* A      = (const float*)d_in[0];
    const float* X      = (const float*)d_in[1];
    const float* coeffs = (const float*)d_in[2];
    const float* wA1    = (const float*)d_in[3];
    const float* wA2    = (const float*)d_in[4];
    const float* w11    = (const float*)d_in[5];
    const float* w12    = (const float*)d_in[6];
    const float* w13    = (const float*)d_in[7];
    const float* w14    = (const float*)d_in[8];
    const float* w15    = (const float*)d_in[9];
    const float* w16    = (const float*)d_in[10];
    const float* w21    = (const float*)d_in[11];
    const float* w22    = (const float*)d_in[12];
    const float* w23    = (const float*)d_in[13];
    const float* w24    = (const float*)d_in[14];
    const float* w25    = (const float*)d_in[15];
    const float* w26    = (const float*)d_in[16];

    float* out = (float*)d_out;
    float* x1o = out + OUT_OFF;

    const int NODE_SMEM = (128*DD + 2*64*68) * (int)sizeof(float);  // 67584
    cudaFuncSetAttribute(k_node, cudaFuncAttributeMaxDynamicSharedMemorySize, NODE_SMEM);

    k_row_stats  <<<2048, 256>>>(A, X, coeffs, wA1);
    k_batch_stats<<<16,   256>>>(X, coeffs, wA2, w12, w15, w16, w22, w25, w26);
    k_node       <<<dim3(8,16), 256, NODE_SMEM>>>(X, w11, w13, w14, w21, w23, w24, x1o);
    k_gemm       <<<dim3(16,16), 256>>>(A, coeffs, out, x1o);
}